// round 1
// baseline (speedup 1.0000x reference)
#include <cuda_runtime.h>
#include <cuda_bf16.h>

// Problem constants (from reference)
#define BATCHES 8
#define NP 4096
#define STRIDE 4
#define KNN 32
#define NS (NP / STRIDE)          // 1024 samples per batch
#define NSAMP (BATCHES * NS)      // 8192
#define NPTS (BATCHES * NP)       // 32768
#define DIN 64
#define H1DIM 128
#define H2DIM 256

// Output layout (float32 concat of the reference tuple)
#define XOUT_OFF   0
#define POS_OFF    (NSAMP * H2DIM)                 // 2097152
#define BATCH_OFF  (POS_OFF + NSAMP * 3)           // 2121728
#define IDX_OFF    (BATCH_OFF + NSAMP)             // 2129920
#define TOTAL_OUT  (IDX_OFF + NSAMP)               // 2138112

// Scratch (static __device__ arrays: no allocation)
__device__ float g_xw1[NPTS * H1DIM];   // 16 MB: x @ W1[:64]
__device__ int   g_nbr[NSAMP * KNN];    // 1 MB : local neighbor indices

// ---------------------------------------------------------------------------
// Kernel 1: xw1[n][j] = sum_f x[n][f] * W1[f][j]   (f < 64)
// ---------------------------------------------------------------------------
__global__ void __launch_bounds__(128) k_xw1(const float* __restrict__ x,
                                             const float* __restrict__ W1) {
    __shared__ float xs[8 * DIN];
    const int p0 = blockIdx.x * 8;
    const int tid = threadIdx.x;   // 128, tid == output channel j
    for (int i = tid; i < 8 * DIN; i += 128) xs[i] = x[p0 * DIN + i];
    __syncthreads();

    float acc[8];
#pragma unroll
    for (int p = 0; p < 8; ++p) acc[p] = 0.f;
#pragma unroll
    for (int f = 0; f < DIN; ++f) {
        float w = W1[f * H1DIM + tid];
#pragma unroll
        for (int p = 0; p < 8; ++p) acc[p] = fmaf(xs[p * DIN + f], w, acc[p]);
    }
#pragma unroll
    for (int p = 0; p < 8; ++p) g_xw1[(p0 + p) * H1DIM + tid] = acc[p];
}

// ---------------------------------------------------------------------------
// Kernel 2: KNN. One block handles 16 samples of one batch.
// d2 computed with the reference's exact rounding (no FMA contraction).
// Selection: 32 rounds of block-wide argmin over (d2, idx) packed u64 keys.
// ---------------------------------------------------------------------------
#define SPB2 16

__device__ __forceinline__ unsigned long long umin64(unsigned long long a,
                                                     unsigned long long b) {
    return b < a ? b : a;
}

__global__ void __launch_bounds__(256) k_knn(const float* __restrict__ pos) {
    extern __shared__ float sm[];
    float* px = sm;
    float* py = sm + NP;
    float* pz = sm + 2 * NP;
    __shared__ unsigned long long warpmin[8];
    __shared__ unsigned long long winner;

    const int tid = threadIdx.x;            // 256
    const int blk = blockIdx.x;             // 8 * 64 = 512
    const int b   = blk / (NS / SPB2);
    const int grp = blk % (NS / SPB2);

    for (int i = tid; i < NP; i += 256) {
        px[i] = pos[(b * NP + i) * 3 + 0];
        py[i] = pos[(b * NP + i) * 3 + 1];
        pz[i] = pos[(b * NP + i) * 3 + 2];
    }
    __syncthreads();

    for (int si = 0; si < SPB2; ++si) {
        const int s_local = grp * SPB2 + si;
        const int c_local = s_local * STRIDE;
        const float ax = px[c_local], ay = py[c_local], az = pz[c_local];
        const float as2 = __fadd_rn(__fadd_rn(__fmul_rn(ax, ax), __fmul_rn(ay, ay)),
                                    __fmul_rn(az, az));

        unsigned long long keys[16];
#pragma unroll
        for (int t = 0; t < 16; ++t) {
            const int i = tid + t * 256;
            const float bx = px[i], by = py[i], bz = pz[i];
            const float bn2 = __fadd_rn(__fadd_rn(__fmul_rn(bx, bx), __fmul_rn(by, by)),
                                        __fmul_rn(bz, bz));
            const float dot = __fadd_rn(__fadd_rn(__fmul_rn(ax, bx), __fmul_rn(ay, by)),
                                        __fmul_rn(az, bz));
            const float d2  = __fadd_rn(__fadd_rn(as2, bn2), -__fmul_rn(2.0f, dot));
            unsigned u = __float_as_uint(d2);
            unsigned kk = (u & 0x80000000u) ? ~u : (u | 0x80000000u);
            keys[t] = (((unsigned long long)kk) << 32) | (unsigned)i;
        }
        unsigned long long lmin = keys[0];
#pragma unroll
        for (int t = 1; t < 16; ++t) lmin = umin64(lmin, keys[t]);

        const int sidx = b * NS + s_local;
        for (int r = 0; r < KNN; ++r) {
            unsigned long long v = lmin;
#pragma unroll
            for (int o = 16; o > 0; o >>= 1)
                v = umin64(v, __shfl_down_sync(0xffffffffu, v, o));
            if ((tid & 31) == 0) warpmin[tid >> 5] = v;
            __syncthreads();
            if (tid == 0) {
                unsigned long long w = warpmin[0];
#pragma unroll
                for (int q = 1; q < 8; ++q) w = umin64(w, warpmin[q]);
                winner = w;
                g_nbr[sidx * KNN + r] = (int)(unsigned)(w & 0xffffffffull);
            }
            __syncthreads();
            const unsigned long long w = winner;
            if (lmin == w) {   // unique owner (idx embedded in key)
#pragma unroll
                for (int t = 0; t < 16; ++t)
                    if (keys[t] == w) keys[t] = 0xffffffffffffffffull;
                lmin = keys[0];
#pragma unroll
                for (int t = 1; t < 16; ++t) lmin = umin64(lmin, keys[t]);
            }
        }
        __syncthreads();
    }
}

// ---------------------------------------------------------------------------
// Kernel 3: MLP + max-pool. One block = 4 samples, 256 threads = 256 output
// channels. W2 column lives in 128 registers/thread. Two neighbors per
// iteration (two independent FFMA chains), h1 double-buffered in smem.
// ---------------------------------------------------------------------------
#define SPB3 4

__global__ void __launch_bounds__(256, 1) k_mlp(const float* __restrict__ pos,
                                                const float* __restrict__ W1,
                                                const float* __restrict__ b1,
                                                const float* __restrict__ W2,
                                                const float* __restrict__ b2,
                                                float* __restrict__ out,
                                                int write_extras) {
    __shared__ float h1s[2][2][H1DIM];  // [parity][neighbor-half][j]
    __shared__ float w1r[3][H1DIM];
    __shared__ float b1s[H1DIM];

    const int tid = threadIdx.x;       // 256, tid == output channel c
    const int blk = blockIdx.x;        // NSAMP/SPB3 = 2048

    if (tid < H1DIM) {
        w1r[0][tid] = W1[64 * H1DIM + tid];
        w1r[1][tid] = W1[65 * H1DIM + tid];
        w1r[2][tid] = W1[66 * H1DIM + tid];
        b1s[tid]    = b1[tid];
    }
    float w2c[H1DIM];
#pragma unroll
    for (int j = 0; j < H1DIM; ++j) w2c[j] = W2[j * H2DIM + tid];
    const float b2c = b2[tid];
    __syncthreads();

    const int j    = tid & 127;
    const int half = tid >> 7;

    for (int si = 0; si < SPB3; ++si) {
        const int s       = blk * SPB3 + si;
        const int b       = s >> 10;            // / NS
        const int s_local = s & (NS - 1);
        const int p       = b * NP + s_local * STRIDE;
        const float psx = pos[3 * p], psy = pos[3 * p + 1], psz = pos[3 * p + 2];

        float acc_max = -3.402823466e38f;
        for (int kk = 0; kk < KNN; kk += 2) {
            const int parity = (kk >> 1) & 1;
            // produce h1 for two neighbors (128 threads each)
            const int nl = g_nbr[s * KNN + kk + half];
            const int g  = b * NP + nl;
            float rx = pos[3 * g]     - psx;
            float ry = pos[3 * g + 1] - psy;
            float rz = pos[3 * g + 2] - psz;
            float v = g_xw1[g * H1DIM + j];
            v = fmaf(rx, w1r[0][j], v);
            v = fmaf(ry, w1r[1][j], v);
            v = fmaf(rz, w1r[2][j], v);
            v += b1s[j];
            h1s[parity][half][j] = fmaxf(v, 0.f);
            __syncthreads();

            const float4* ha = (const float4*)h1s[parity][0];
            const float4* hb = (const float4*)h1s[parity][1];
            float acc_a = b2c, acc_b = b2c;
#pragma unroll
            for (int q = 0; q < 32; ++q) {
                const float4 a  = ha[q];
                const float4 bb = hb[q];
                acc_a = fmaf(a.x,  w2c[4 * q + 0], acc_a);
                acc_b = fmaf(bb.x, w2c[4 * q + 0], acc_b);
                acc_a = fmaf(a.y,  w2c[4 * q + 1], acc_a);
                acc_b = fmaf(bb.y, w2c[4 * q + 1], acc_b);
                acc_a = fmaf(a.z,  w2c[4 * q + 2], acc_a);
                acc_b = fmaf(bb.z, w2c[4 * q + 2], acc_b);
                acc_a = fmaf(a.w,  w2c[4 * q + 3], acc_a);
                acc_b = fmaf(bb.w, w2c[4 * q + 3], acc_b);
            }
            acc_max = fmaxf(acc_max, fmaxf(acc_a, 0.f));
            acc_max = fmaxf(acc_max, fmaxf(acc_b, 0.f));
            // no trailing sync needed: next iteration writes the other buffer
        }
        out[XOUT_OFF + s * H2DIM + tid] = acc_max;
        if (write_extras) {
            if (tid < 3)  out[POS_OFF + s * 3 + tid] = pos[3 * p + tid];
            if (tid == 3) out[BATCH_OFF + s] = (float)b;
            if (tid == 4) out[IDX_OFF + s]   = (float)p;
        }
    }
}

// ---------------------------------------------------------------------------
extern "C" void kernel_launch(void* const* d_in, const int* in_sizes, int n_in,
                              void* d_out, int out_size) {
    const float* x   = (const float*)d_in[0];
    const float* pos = (const float*)d_in[1];
    // d_in[2] = batch (int64), derivable -> unused
    const float* W1  = (const float*)d_in[3];
    const float* b1  = (const float*)d_in[4];
    const float* W2  = (const float*)d_in[5];
    const float* b2  = (const float*)d_in[6];
    float* out = (float*)d_out;

    const int write_extras = (out_size >= TOTAL_OUT) ? 1 : 0;

    k_xw1<<<NPTS / 8, 128>>>(x, W1);

    const int smem2 = 3 * NP * (int)sizeof(float);   // 48 KB
    cudaFuncSetAttribute(k_knn, cudaFuncAttributeMaxDynamicSharedMemorySize, smem2);
    k_knn<<<BATCHES * (NS / SPB2), 256, smem2>>>(pos);

    k_mlp<<<NSAMP / SPB3, 256>>>(pos, W1, b1, W2, b2, out, write_extras);
}